// round 11
// baseline (speedup 1.0000x reference)
#include <cuda_runtime.h>
#include <cuda_bf16.h>
#include <cstdint>

// Problem constants
#define NB     4
#define CIN    512
#define COUT   256
#define DDIM   256
#define SP     16384            // H*W
#define NSPLIT 16
#define SCHUNK (SP / NSPLIT)    // 1024

#define TILE   128
#define KC     64
#define TILE_BYTES (TILE * KC * 2)      // 16384

// ------------------- global scratch (bf16 split arrays) ---------------------
__device__ unsigned short g_fT1[(size_t)NB * SP * CIN];   // featT [n][s][cin]
__device__ unsigned short g_fT2[(size_t)NB * SP * CIN];
__device__ unsigned short g_fT3[(size_t)NB * SP * CIN];
__device__ unsigned short g_q1[(size_t)NB * DDIM * SP];   // q [n][d][s]
__device__ unsigned short g_q2[(size_t)NB * DDIM * SP];
__device__ unsigned short g_q3[(size_t)NB * DDIM * SP];
__device__ unsigned short g_qT1[(size_t)NB * SP * DDIM];  // qT [n][s][d]
__device__ unsigned short g_qT2[(size_t)NB * SP * DDIM];
__device__ unsigned short g_k1[(size_t)NB * COUT * SP];   // K [n][c][s]
__device__ unsigned short g_k2[(size_t)NB * COUT * SP];
__device__ unsigned short g_k3[(size_t)NB * COUT * SP];
__device__ unsigned short g_w11[COUT * CIN];
__device__ unsigned short g_w12[COUT * CIN];
__device__ unsigned short g_w13[COUT * CIN];
__device__ unsigned short g_m1[(size_t)NB * COUT * DDIM]; // M [n][o][d]
__device__ unsigned short g_m2[(size_t)NB * COUT * DDIM];
__device__ float g_epart[(size_t)NB * NSPLIT * DDIM * COUT];  // 16 MiB
__device__ float g_att[(size_t)NB * DDIM * COUT];             // 1 MiB

// ---------------- helpers ---------------------------------------------------
__device__ __forceinline__ uint32_t smem_u32(const void* p) {
    uint32_t a;
    asm("{ .reg .u64 t; cvta.to.shared.u64 t, %1; cvt.u32.u64 %0, t; }"
        : "=r"(a) : "l"(p));
    return a;
}
__device__ __forceinline__ uint32_t swz(uint32_t b) { return b ^ ((b >> 3) & 0x70); }

__device__ __forceinline__ void ldsm4(uint32_t* r, uint32_t addr)
{
    asm volatile("ldmatrix.sync.aligned.m8n8.x4.shared.b16 {%0,%1,%2,%3}, [%4];"
                 : "=r"(r[0]), "=r"(r[1]), "=r"(r[2]), "=r"(r[3]) : "r"(addr));
}
__device__ __forceinline__ void mma16816(float* c, const uint32_t* a, const uint32_t* b)
{
    asm volatile(
        "mma.sync.aligned.m16n8k16.row.col.f32.bf16.bf16.f32 "
        "{%0,%1,%2,%3}, {%4,%5,%6,%7}, {%8,%9}, {%0,%1,%2,%3};"
        : "+f"(c[0]), "+f"(c[1]), "+f"(c[2]), "+f"(c[3])
        : "r"(a[0]), "r"(a[1]), "r"(a[2]), "r"(a[3]), "r"(b[0]), "r"(b[1]));
}
#define CP16(dst, src) asm volatile( \
    "cp.async.cg.shared.global [%0], [%1], 16;" :: "r"(dst), "l"(src) : "memory")
#define CP_COMMIT() asm volatile("cp.async.commit_group;" ::: "memory")
#define CP_WAIT1()  asm volatile("cp.async.wait_group 1;" ::: "memory")
#define CP_WAIT0()  asm volatile("cp.async.wait_group 0;" ::: "memory")

// Split fp32 -> 3 bf16 components (x ~= h1 + h2 + h3)
__device__ __forceinline__ void split3(float x, unsigned short& a,
                                       unsigned short& b, unsigned short& c)
{
    __nv_bfloat16 h1 = __float2bfloat16_rn(x);
    float r = x - __bfloat162float(h1);
    __nv_bfloat16 h2 = __float2bfloat16_rn(r);
    float r2 = r - __bfloat162float(h2);
    __nv_bfloat16 h3 = __float2bfloat16_rn(r2);
    a = __bfloat16_as_ushort(h1);
    b = __bfloat16_as_ushort(h2);
    c = __bfloat16_as_ushort(h3);
}

// ---------------------------------------------------------------------------
// Elementwise split: in fp32 -> 3 bf16 arrays (same layout), float4 granules.
// ---------------------------------------------------------------------------
__global__ void __launch_bounds__(256) split_clean_k(
    const float4* __restrict__ in, uint2* __restrict__ o1,
    uint2* __restrict__ o2, uint2* __restrict__ o3, size_t n4)
{
    size_t i = (size_t)blockIdx.x * 256 + threadIdx.x;
    if (i >= n4) return;
    float4 v = in[i];
    unsigned short a1,a2,a3,b1,b2,b3,c1,c2,c3,d1,d2,d3;
    split3(v.x, a1,a2,a3); split3(v.y, b1,b2,b3);
    split3(v.z, c1,c2,c3); split3(v.w, d1,d2,d3);
    o1[i] = make_uint2((uint32_t)a1 | ((uint32_t)b1 << 16),
                       (uint32_t)c1 | ((uint32_t)d1 << 16));
    o2[i] = make_uint2((uint32_t)a2 | ((uint32_t)b2 << 16),
                       (uint32_t)c2 | ((uint32_t)d2 << 16));
    o3[i] = make_uint2((uint32_t)a3 | ((uint32_t)b3 << 16),
                       (uint32_t)c3 | ((uint32_t)d3 << 16));
}

// ---------------------------------------------------------------------------
// Transpose+split: in [R, SP] fp32 (per batch) -> out [SP, R] bf16 x NOUT.
// Tile 64(r) x 32(s). grid (SP/32, R/64, NB), 256 threads.
// ---------------------------------------------------------------------------
template <int NOUT>
__global__ void __launch_bounds__(256) split_trans_k(
    const float* __restrict__ in, unsigned short* __restrict__ o1,
    unsigned short* __restrict__ o2, unsigned short* __restrict__ o3, int R)
{
    const int nB = blockIdx.z;
    const float* src = in + (size_t)nB * R * SP;
    const int r0 = blockIdx.y * 64, s0 = blockIdx.x * 32;
    __shared__ float t[64][33];
    const int tid = threadIdx.x;
    const int sx = tid & 31, ry = tid >> 5;
#pragma unroll
    for (int w = 0; w < 8; w++)
        t[ry + w * 8][sx] = src[(size_t)(r0 + ry + w * 8) * SP + s0 + sx];
    __syncthreads();
    const int up = tid & 31;     // r-pair index
    const int sr0 = tid >> 5;    // 0..7
    const size_t obase = (size_t)nB * SP * R;
#pragma unroll
    for (int w = 0; w < 4; w++) {
        const int srow = sr0 + w * 8;
        float v0 = t[up * 2][srow], v1 = t[up * 2 + 1][srow];
        unsigned short a1,a2,a3,b1,b2,b3;
        split3(v0, a1,a2,a3); split3(v1, b1,b2,b3);
        size_t off = obase + (size_t)(s0 + srow) * R + r0 + up * 2;
        *(uint32_t*)(o1 + off) = (uint32_t)a1 | ((uint32_t)b1 << 16);
        *(uint32_t*)(o2 + off) = (uint32_t)a2 | ((uint32_t)b2 << 16);
        if (NOUT == 3)
            *(uint32_t*)(o3 + off) = (uint32_t)a3 | ((uint32_t)b3 << 16);
    }
}

// ---------------------------------------------------------------------------
// Tensor-core GEMM, bf16-split operands preconverted in gmem, cp.async
// double-buffered fills, warp-level mma.sync.
//   MODE 0: conv1  A=w1 splits, B=featT splits, epi BN+ReLU -> g_k splits
//   MODE 1: energy A=q splits,  B=g_k splits,   epi fp32 partials
//   MODE 2: conv2  A=g_m splits (2), B=qT splits (2), epi +bias -> out
// 128x128 tile, 8 warps (2m x 4n), warp tile 64x32.
// ---------------------------------------------------------------------------
template <int MODE>
__global__ void __launch_bounds__(256) tc_gemm(
    float* __restrict__ outp,
    const float* __restrict__ p0, const float* __restrict__ p1,
    const float* __restrict__ p2, const float* __restrict__ p3)
{
    constexpr int NSPL  = (MODE == 2) ? 2 : 3;
    constexpr int NPROD = (MODE == 2) ? 4 : 6;
    constexpr int BUFB  = 2 * NSPL * TILE_BYTES;

    extern __shared__ char sm[];
    const uint32_t smb = smem_u32(sm);
    const int tid = threadIdx.x;
    const int wid = tid >> 5;
    const int lane = tid & 31;
    const int warp_m = wid >> 2;
    const int warp_n = wid & 3;

    const unsigned short* Ab[3];
    const unsigned short* Bb[3];
    float* C = nullptr;
    int lda, ldb, Kdim;
    size_t kbo = 0;

    if (MODE == 0) {
        const int n = blockIdx.z;
        Ab[0] = g_w11; Ab[1] = g_w12; Ab[2] = g_w13; lda = CIN;
        const size_t bo = (size_t)n * SP * CIN;
        Bb[0] = g_fT1 + bo; Bb[1] = g_fT2 + bo; Bb[2] = g_fT3 + bo; ldb = CIN;
        Kdim = CIN;
        kbo = (size_t)n * COUT * SP;
    } else if (MODE == 1) {
        const int n = blockIdx.z >> 4, sp = blockIdx.z & 15;
        const size_t ao = (size_t)n * DDIM * SP + (size_t)sp * SCHUNK;
        Ab[0] = g_q1 + ao; Ab[1] = g_q2 + ao; Ab[2] = g_q3 + ao; lda = SP;
        const size_t bo = (size_t)n * COUT * SP + (size_t)sp * SCHUNK;
        Bb[0] = g_k1 + bo; Bb[1] = g_k2 + bo; Bb[2] = g_k3 + bo; ldb = SP;
        C = g_epart + (size_t)blockIdx.z * DDIM * COUT;
        Kdim = SCHUNK;
    } else {
        const int n = blockIdx.z;
        const size_t ao = (size_t)n * COUT * DDIM;
        Ab[0] = g_m1 + ao; Ab[1] = g_m2 + ao; Ab[2] = nullptr; lda = DDIM;
        const size_t bo = (size_t)n * SP * DDIM;
        Bb[0] = g_qT1 + bo; Bb[1] = g_qT2 + bo; Bb[2] = nullptr; ldb = DDIM;
        C = outp + (size_t)n * COUT * SP;
        Kdim = DDIM;
    }
    const int tM = blockIdx.y * TILE;
    const int tN = blockIdx.x * TILE;

    // fill thread mapping: 4 rows x 16B per split per operand
    const int frow = tid >> 3;           // 0..31
    const int fcs  = (tid & 7) * 8;      // bf16 elem offset (16B)
    const uint32_t fsw = swz((uint32_t)frow * 128u + (uint32_t)(tid & 7) * 16u);

    auto issue = [&](int ch, int buf) {
        const uint32_t base = smb + (uint32_t)buf * BUFB;
#pragma unroll
        for (int p = 0; p < NSPL; p++) {
#pragma unroll
            for (int w = 0; w < 4; w++) {
                const int r = frow + w * 32;
                const uint32_t dsw = fsw + (uint32_t)(w * 32 * 128);
                // note: swz only touches bits 4-6; r*128 adds bits >=7+? 32*128=4096 ok
                CP16(base + p * TILE_BYTES + dsw,
                     Ab[p] + (size_t)(tM + r) * lda + ch * KC + fcs);
                CP16(base + (NSPL + p) * TILE_BYTES + dsw,
                     Bb[p] + (size_t)(tN + r) * ldb + ch * KC + fcs);
            }
        }
    };

    float acc[4][4][4];
#pragma unroll
    for (int i = 0; i < 4; i++)
#pragma unroll
        for (int j = 0; j < 4; j++)
#pragma unroll
            for (int v = 0; v < 4; v++) acc[i][j][v] = 0.f;

    const int a_row_c = warp_m * 64 + ((tid >> 3) & 1) * 8 + (tid & 7);
    const int a_k_c   = ((tid >> 4) & 1) * 16;
    const int b_row_c = warp_n * 32 + ((tid >> 4) & 1) * 8 + (tid & 7);
    const int b_k_c   = ((tid >> 3) & 1) * 16;

    const int pa6[6] = {0, 0, 1, 1, 0, 2};
    const int pb6[6] = {0, 1, 0, 1, 2, 0};
    const int pa4[4] = {0, 0, 1, 1};
    const int pb4[4] = {0, 1, 0, 1};

    const int nch = Kdim / KC;
    issue(0, 0);
    CP_COMMIT();

    for (int ch = 0; ch < nch; ch++) {
        if (ch + 1 < nch) {
            issue(ch + 1, (ch + 1) & 1);
            CP_COMMIT();
            CP_WAIT1();
        } else {
            CP_WAIT0();
        }
        __syncthreads();

        const uint32_t cb = smb + (uint32_t)(ch & 1) * BUFB;
#pragma unroll
        for (int p = 0; p < NPROD; p++) {
            const int ia = (NSPL == 3) ? pa6[p] : pa4[p];
            const int ib = (NSPL == 3) ? pb6[p] : pb4[p];
            const uint32_t baseA = cb + (uint32_t)ia * TILE_BYTES;
            const uint32_t baseB = cb + (uint32_t)(NSPL + ib) * TILE_BYTES;
#pragma unroll
            for (int ks = 0; ks < 4; ks++) {
                uint32_t af[4][4];
#pragma unroll
                for (int mf = 0; mf < 4; mf++)
                    ldsm4(af[mf], baseA + swz((uint32_t)(a_row_c + mf * 16) * 128u
                                              + (uint32_t)(a_k_c + ks * 32)));
                uint32_t bf[2][4];
#pragma unroll
                for (int jj = 0; jj < 2; jj++)
                    ldsm4(bf[jj], baseB + swz((uint32_t)(b_row_c + jj * 16) * 128u
                                              + (uint32_t)(b_k_c + ks * 32)));
#pragma unroll
                for (int mf = 0; mf < 4; mf++)
#pragma unroll
                    for (int nf = 0; nf < 4; nf++)
                        mma16816(acc[mf][nf], af[mf], &bf[nf >> 1][(nf & 1) * 2]);
            }
        }
        __syncthreads();
    }

    // -------------------- epilogue --------------------
#pragma unroll
    for (int mf = 0; mf < 4; mf++) {
        const int r0 = tM + warp_m * 64 + mf * 16 + (lane >> 2);
        const int r1 = r0 + 8;
        float sc0 = 1.f, sh0 = 0.f, sc1 = 1.f, sh1 = 0.f;
        if (MODE == 0) {
            sc0 = p0[r0] * rsqrtf(p3[r0] + 1e-5f);
            sh0 = p1[r0] - p2[r0] * sc0;
            sc1 = p0[r1] * rsqrtf(p3[r1] + 1e-5f);
            sh1 = p1[r1] - p2[r1] * sc1;
        } else if (MODE == 2) {
            sh0 = p0[r0];
            sh1 = p0[r1];
        }
#pragma unroll
        for (int nf = 0; nf < 4; nf++) {
            const int col = tN + warp_n * 32 + nf * 8 + (lane & 3) * 2;
            float v0 = acc[mf][nf][0], v1 = acc[mf][nf][1];
            float v2 = acc[mf][nf][2], v3 = acc[mf][nf][3];
            if (MODE == 0) {
                v0 = fmaxf(v0 * sc0 + sh0, 0.f);
                v1 = fmaxf(v1 * sc0 + sh0, 0.f);
                v2 = fmaxf(v2 * sc1 + sh1, 0.f);
                v3 = fmaxf(v3 * sc1 + sh1, 0.f);
                unsigned short a1,a2,a3,b1,b2,b3;
                size_t o0 = kbo + (size_t)r0 * SP + col;
                split3(v0, a1,a2,a3); split3(v1, b1,b2,b3);
                *(uint32_t*)(g_k1 + o0) = (uint32_t)a1 | ((uint32_t)b1 << 16);
                *(uint32_t*)(g_k2 + o0) = (uint32_t)a2 | ((uint32_t)b2 << 16);
                *(uint32_t*)(g_k3 + o0) = (uint32_t)a3 | ((uint32_t)b3 << 16);
                size_t o1 = kbo + (size_t)r1 * SP + col;
                split3(v2, a1,a2,a3); split3(v3, b1,b2,b3);
                *(uint32_t*)(g_k1 + o1) = (uint32_t)a1 | ((uint32_t)b1 << 16);
                *(uint32_t*)(g_k2 + o1) = (uint32_t)a2 | ((uint32_t)b2 << 16);
                *(uint32_t*)(g_k3 + o1) = (uint32_t)a3 | ((uint32_t)b3 << 16);
            } else if (MODE == 1) {
                *(float2*)(C + (size_t)r0 * COUT + col) = make_float2(v0, v1);
                *(float2*)(C + (size_t)r1 * COUT + col) = make_float2(v2, v3);
            } else {
                v0 += sh0; v1 += sh0; v2 += sh1; v3 += sh1;
                *(float2*)(C + (size_t)r0 * SP + col) = make_float2(v0, v1);
                *(float2*)(C + (size_t)r1 * SP + col) = make_float2(v2, v3);
            }
        }
    }
}

// ---------------------------------------------------------------------------
// Fused split-reduce + softmax: softmax(max-e) == exp(min-e)/sum.
// ---------------------------------------------------------------------------
__global__ void __launch_bounds__(256) softmax_k()
{
    const int nd = blockIdx.x;
    const int n = nd / DDIM;
    const int d = nd % DDIM;
    const int c = threadIdx.x;

    float e = 0.f;
#pragma unroll
    for (int s = 0; s < NSPLIT; s++)
        e += g_epart[((size_t)(n * NSPLIT + s) * DDIM + d) * COUT + c];

    __shared__ float red[256];
    red[c] = e;
    __syncthreads();
    for (int off = 128; off > 0; off >>= 1) {
        if (c < off) red[c] = fminf(red[c], red[c + off]);
        __syncthreads();
    }
    const float emin = red[0];
    __syncthreads();

    const float ex = expf(emin - e);
    red[c] = ex;
    __syncthreads();
    for (int off = 128; off > 0; off >>= 1) {
        if (c < off) red[c] += red[c + off];
        __syncthreads();
    }
    g_att[(size_t)nd * COUT + c] = ex / red[0];
}

// ---------------------------------------------------------------------------
// M[o,d] = sum_c W2[o,c] * att[d,c]; epilogue writes bf16 2-way splits.
// ---------------------------------------------------------------------------
__global__ void __launch_bounds__(256) mmul_k(const float* __restrict__ w2)
{
    const int n = blockIdx.z;
    const float* A = w2;
    const float* B = g_att + (size_t)n * DDIM * COUT;

    const int tI = blockIdx.y * 32;
    const int tJ = blockIdx.x * 32;

    __shared__ float As[32][33];
    __shared__ float Bs[32][33];

    const int tid = threadIdx.x;
    const int r  = tid >> 3;
    const int c4 = (tid & 7) * 4;
    const int io = (tid >> 4) * 2;
    const int jo = (tid & 15) * 2;

    float acc[2][2] = {{0.f, 0.f}, {0.f, 0.f}};

    for (int k0 = 0; k0 < COUT; k0 += 32) {
        float4 av = *(const float4*)(A + (size_t)(tI + r) * COUT + k0 + c4);
        float4 bv = *(const float4*)(B + (size_t)(tJ + r) * COUT + k0 + c4);
        __syncthreads();
        As[c4 + 0][r] = av.x; As[c4 + 1][r] = av.y;
        As[c4 + 2][r] = av.z; As[c4 + 3][r] = av.w;
        Bs[c4 + 0][r] = bv.x; Bs[c4 + 1][r] = bv.y;
        Bs[c4 + 2][r] = bv.z; Bs[c4 + 3][r] = bv.w;
        __syncthreads();
#pragma unroll
        for (int k = 0; k < 32; k++) {
            float a0 = As[k][io], a1 = As[k][io + 1];
            float b0 = Bs[k][jo], b1 = Bs[k][jo + 1];
            acc[0][0] = fmaf(a0, b0, acc[0][0]);
            acc[0][1] = fmaf(a0, b1, acc[0][1]);
            acc[1][0] = fmaf(a1, b0, acc[1][0]);
            acc[1][1] = fmaf(a1, b1, acc[1][1]);
        }
    }
#pragma unroll
    for (int i = 0; i < 2; i++)
#pragma unroll
        for (int j = 0; j < 2; j++) {
            unsigned short a, b, cc;
            split3(acc[i][j], a, b, cc);
            const size_t off = (size_t)n * COUT * DDIM
                             + (size_t)(tI + io + i) * DDIM + tJ + jo + j;
            g_m1[off] = a;
            g_m2[off] = b;
        }
}

// ---------------------------------------------------------------------------
extern "C" void kernel_launch(void* const* d_in, const int* in_sizes, int n_in,
                              void* d_out, int out_size)
{
    const float* feat  = (const float*)d_in[0];
    const float* q     = (const float*)d_in[1];
    const float* w1    = (const float*)d_in[2];
    const float* gamma = (const float*)d_in[3];
    const float* beta  = (const float*)d_in[4];
    const float* mean  = (const float*)d_in[5];
    const float* var   = (const float*)d_in[6];
    const float* w2    = (const float*)d_in[7];
    const float* b2    = (const float*)d_in[8];
    float* out = (float*)d_out;

    // symbol addresses for conversion kernels
    void *q1, *q2, *q3, *w11, *w12, *w13, *fT1, *fT2, *fT3, *qT1, *qT2;
    cudaGetSymbolAddress(&q1, g_q1);   cudaGetSymbolAddress(&q2, g_q2);
    cudaGetSymbolAddress(&q3, g_q3);
    cudaGetSymbolAddress(&w11, g_w11); cudaGetSymbolAddress(&w12, g_w12);
    cudaGetSymbolAddress(&w13, g_w13);
    cudaGetSymbolAddress(&fT1, g_fT1); cudaGetSymbolAddress(&fT2, g_fT2);
    cudaGetSymbolAddress(&fT3, g_fT3);
    cudaGetSymbolAddress(&qT1, g_qT1); cudaGetSymbolAddress(&qT2, g_qT2);

    const int SMEM0 = 2 * 6 * TILE_BYTES;   // 196608
    const int SMEM2 = 2 * 4 * TILE_BYTES;   // 131072
    static bool attr_done = false;
    if (!attr_done) {
        cudaFuncSetAttribute(tc_gemm<0>, cudaFuncAttributeMaxDynamicSharedMemorySize, SMEM0);
        cudaFuncSetAttribute(tc_gemm<1>, cudaFuncAttributeMaxDynamicSharedMemorySize, SMEM0);
        cudaFuncSetAttribute(tc_gemm<2>, cudaFuncAttributeMaxDynamicSharedMemorySize, SMEM2);
        attr_done = true;
    }

    // 0a) q -> clean splits (for energy A)
    {
        size_t n4 = (size_t)NB * DDIM * SP / 4;
        split_clean_k<<<(unsigned)((n4 + 255) / 256), 256>>>(
            (const float4*)q, (uint2*)q1, (uint2*)q2, (uint2*)q3, n4);
    }
    // 0b) w1 -> clean splits
    {
        size_t n4 = (size_t)COUT * CIN / 4;
        split_clean_k<<<(unsigned)((n4 + 255) / 256), 256>>>(
            (const float4*)w1, (uint2*)w11, (uint2*)w12, (uint2*)w13, n4);
    }
    // 0c) feat -> transposed splits [n][s][cin]
    split_trans_k<3><<<dim3(SP / 32, CIN / 64, NB), 256>>>(
        feat, (unsigned short*)fT1, (unsigned short*)fT2, (unsigned short*)fT3, CIN);
    // 0d) q -> transposed splits [n][s][d] (2-way, for conv2 B)
    split_trans_k<2><<<dim3(SP / 32, DDIM / 64, NB), 256>>>(
        q, (unsigned short*)qT1, (unsigned short*)qT2, nullptr, DDIM);

    // 1) conv1: K = relu(bn(W1 @ F)) -> g_k splits
    tc_gemm<0><<<dim3(SP / TILE, COUT / TILE, NB), 256, SMEM0>>>(
        nullptr, gamma, beta, mean, var);

    // 2) energy partials: E[d,c] = Q . K^T, split-S
    tc_gemm<1><<<dim3(COUT / TILE, DDIM / TILE, NB * NSPLIT), 256, SMEM0>>>(
        nullptr, nullptr, nullptr, nullptr, nullptr);

    // 3) reduce + softmax -> attention
    softmax_k<<<NB * DDIM, 256>>>();

    // 4) M = W2 @ att^T -> g_m splits
    mmul_k<<<dim3(DDIM / 32, COUT / 32, NB), 256>>>(w2);

    // 5) out = M @ Q + b2
    tc_gemm<2><<<dim3(SP / TILE, COUT / TILE, NB), 256, SMEM2>>>(
        out, b2, nullptr, nullptr, nullptr);
}

// round 12
// speedup vs baseline: 1.8257x; 1.8257x over previous
#include <cuda_runtime.h>
#include <cuda_fp16.h>
#include <cstdint>

// Problem constants
#define NB     4
#define CIN    512
#define COUT   256
#define DDIM   256
#define SP     16384            // H*W
#define NSPLIT 16
#define SCHUNK (SP / NSPLIT)    // 1024

#define TILE   128
#define KC     64               // K per chunk (fp16: 128B rows = SW128 atom)
#define TILE_BYTES (TILE * KC * 2)      // 16384
#define SMEM_DYN   (4 * TILE_BYTES)     // 65536

// ------------------- global scratch -----------------------------------------
__device__ unsigned short g_k1[(size_t)NB * COUT * SP];   // K fp16 split hi
__device__ unsigned short g_k2[(size_t)NB * COUT * SP];   // K fp16 split lo
__device__ unsigned short g_m1[(size_t)NB * COUT * DDIM]; // M fp16 split hi
__device__ unsigned short g_m2[(size_t)NB * COUT * DDIM]; // M fp16 split lo
__device__ float g_epart[(size_t)NB * NSPLIT * DDIM * COUT];  // 16 MiB
__device__ float g_att[(size_t)NB * DDIM * COUT];             // 1 MiB

// ---------------- helpers ---------------------------------------------------
__device__ __forceinline__ uint32_t smem_u32(const void* p) {
    uint32_t a;
    asm("{ .reg .u64 t; cvta.to.shared.u64 t, %1; cvt.u32.u64 %0, t; }"
        : "=r"(a) : "l"(p));
    return a;
}
__device__ __forceinline__ uint32_t swz(uint32_t b) { return b ^ ((b >> 3) & 0x70); }

__device__ __forceinline__ void ldsm4(uint32_t* r, uint32_t addr)
{
    asm volatile("ldmatrix.sync.aligned.m8n8.x4.shared.b16 {%0,%1,%2,%3}, [%4];"
                 : "=r"(r[0]), "=r"(r[1]), "=r"(r[2]), "=r"(r[3]) : "r"(addr));
}
// D += A*B  (m16n8k16, fp16 in, fp32 acc)
__device__ __forceinline__ void mma16816(float* c, const uint32_t* a, const uint32_t* b)
{
    asm volatile(
        "mma.sync.aligned.m16n8k16.row.col.f32.f16.f16.f32 "
        "{%0,%1,%2,%3}, {%4,%5,%6,%7}, {%8,%9}, {%0,%1,%2,%3};"
        : "+f"(c[0]), "+f"(c[1]), "+f"(c[2]), "+f"(c[3])
        : "r"(a[0]), "r"(a[1]), "r"(a[2]), "r"(a[3]), "r"(b[0]), "r"(b[1]));
}
#define CP16(dst, src) asm volatile( \
    "cp.async.cg.shared.global [%0], [%1], 16;" :: "r"(dst), "l"(src) : "memory")
#define CP_COMMIT() asm volatile("cp.async.commit_group;" ::: "memory")
#define CP_WAIT0()  asm volatile("cp.async.wait_group 0;" ::: "memory")

// Split fp32 -> 2 fp16 components (x ~= h1 + h2)
__device__ __forceinline__ void split2(float x, unsigned short& a, unsigned short& b)
{
    __half h1 = __float2half_rn(x);
    float r = x - __half2float(h1);
    __half h2 = __float2half_rn(r);
    a = __half_as_ushort(h1);
    b = __half_as_ushort(h2);
}

// Clean fill from fp32: tile[r][k] = g[r][k], SW128-swizzled, 2 split tiles.
__device__ __forceinline__ void fill_clean2(char* tiles, const float* g, int ld, int tid)
{
    const int c16 = tid & 15;            // float4 index within 64-col row
    const int rb  = tid >> 4;            // row base 0..15
#pragma unroll
    for (int it = 0; it < 8; it++) {
        const int r = rb + it * 16;
        float4 v = *(const float4*)(g + (size_t)r * ld + c16 * 4);
        unsigned long long u1 = 0, u2 = 0;
        const float xs[4] = {v.x, v.y, v.z, v.w};
#pragma unroll
        for (int j = 0; j < 4; j++) {
            unsigned short a, b;
            split2(xs[j], a, b);
            u1 |= (unsigned long long)a << (16 * j);
            u2 |= (unsigned long long)b << (16 * j);
        }
        const uint32_t sw = swz((uint32_t)r * 128u + (uint32_t)c16 * 8u);
        *(unsigned long long*)(tiles + sw)              = u1;
        *(unsigned long long*)(tiles + TILE_BYTES + sw) = u2;
    }
}

// Transposed fill from fp32: tile[n][k] = g[k][n]. g at (k-row 0, col n0).
__device__ __forceinline__ void fill_trans2(char* tiles, const float* g, int ld, int tid)
{
    const int bk = (tid >> 2) & 15;                    // k-block 0..15
    const int bn0 = (tid & 3) | ((tid >> 6) << 2);     // n-block 0..7
#pragma unroll
    for (int it = 0; it < 2; it++) {
        const int bn = bn0 + it * 16;
        float4 rowv[4];
#pragma unroll
        for (int j = 0; j < 4; j++)
            rowv[j] = *(const float4*)(g + (size_t)(bk * 4 + j) * ld + bn * 4);
        const float* rp = (const float*)rowv;
#pragma unroll
        for (int i = 0; i < 4; i++) {
            unsigned long long u1 = 0, u2 = 0;
#pragma unroll
            for (int j = 0; j < 4; j++) {
                unsigned short a, b;
                split2(rp[j * 4 + i], a, b);
                u1 |= (unsigned long long)a << (16 * j);
                u2 |= (unsigned long long)b << (16 * j);
            }
            const uint32_t sw = swz((uint32_t)(bn * 4 + i) * 128u + (uint32_t)bk * 8u);
            *(unsigned long long*)(tiles + sw)              = u1;
            *(unsigned long long*)(tiles + TILE_BYTES + sw) = u2;
        }
    }
}

// Copy fill from preexisting fp16 split arrays via cp.async (caller commits/waits).
__device__ __forceinline__ void copy2(uint32_t dstbase,
    const unsigned short* s1, const unsigned short* s2,
    int row0, int ld, int koff, int tid)
{
    const int r = tid >> 1;              // 0..127
    const int h = tid & 1;
#pragma unroll
    for (int j = 0; j < 4; j++) {
        const int u = h * 4 + j;         // 16B unit within 128B row
        const uint32_t dsw = swz((uint32_t)r * 128u + (uint32_t)u * 16u);
        const size_t so = (size_t)(row0 + r) * ld + koff + u * 8;
        CP16(dstbase + dsw, s1 + so);
        CP16(dstbase + TILE_BYTES + dsw, s2 + so);
    }
}

// ---------------------------------------------------------------------------
// Tensor-core GEMM, fp16 2-way split, 3 products, warp-level mma.sync.
//   MODE 0: conv1  A=w1(fp32 clean), B=feat(fp32 trans), epi BN+ReLU -> K splits
//   MODE 1: energy A=q(fp32 clean),  B=K splits(copy),   epi fp32 partials
//   MODE 2: conv2  A=M splits(copy), B=q(fp32 trans),    epi +bias -> out
// 128x128 tile, 8 warps (2m x 4n), warp tile 64x32, single-buffered 64 KiB.
// ---------------------------------------------------------------------------
template <int MODE>
__global__ void __launch_bounds__(256) tc_gemm(
    const float* __restrict__ Af32, const float* __restrict__ Bf32,
    float* __restrict__ outp,
    const float* __restrict__ p0, const float* __restrict__ p1,
    const float* __restrict__ p2, const float* __restrict__ p3)
{
    extern __shared__ char sm[];
    const uint32_t smb = smem_u32(sm);
    const int tid = threadIdx.x;
    const int wid = tid >> 5;
    const int lane = tid & 31;
    const int warp_m = wid >> 2;
    const int warp_n = wid & 3;

    const float* A = nullptr;
    const float* B = nullptr;
    const unsigned short *Ah1 = nullptr, *Ah2 = nullptr;
    const unsigned short *Bh1 = nullptr, *Bh2 = nullptr;
    float* C = nullptr;
    int lda = 0, ldb = 0, Kdim = 0;
    size_t kbo = 0;

    if (MODE == 0) {
        const int n = blockIdx.z;
        A = Af32; lda = CIN;                         // w1 [COUT][CIN]
        B = Bf32 + (size_t)n * CIN * SP; ldb = SP;   // feat [CIN][SP]
        Kdim = CIN;
        kbo = (size_t)n * COUT * SP;
    } else if (MODE == 1) {
        const int n = blockIdx.z >> 4, sp = blockIdx.z & 15;
        A = Af32 + (size_t)n * DDIM * SP + (size_t)sp * SCHUNK; lda = SP;  // q
        const size_t bo = (size_t)n * COUT * SP + (size_t)sp * SCHUNK;
        Bh1 = g_k1 + bo; Bh2 = g_k2 + bo; ldb = SP;
        C = g_epart + (size_t)blockIdx.z * DDIM * COUT;
        Kdim = SCHUNK;
    } else {
        const int n = blockIdx.z;
        const size_t ao = (size_t)n * COUT * DDIM;
        Ah1 = g_m1 + ao; Ah2 = g_m2 + ao; lda = DDIM;
        B = Bf32 + (size_t)n * DDIM * SP; ldb = SP;  // q [DDIM][SP] (transposed use)
        C = outp + (size_t)n * COUT * SP;
        Kdim = DDIM;
    }
    const int tM = blockIdx.y * TILE;
    const int tN = blockIdx.x * TILE;

    char* smA = sm;                       // 2 split tiles
    char* smB = sm + 2 * TILE_BYTES;      // 2 split tiles

    float acc[4][4][4];
#pragma unroll
    for (int i = 0; i < 4; i++)
#pragma unroll
        for (int j = 0; j < 4; j++)
#pragma unroll
            for (int v = 0; v < 4; v++) acc[i][j][v] = 0.f;

    const int a_row_c = warp_m * 64 + ((tid >> 3) & 1) * 8 + (tid & 7);
    const int a_k_c   = ((tid >> 4) & 1) * 16;
    const int b_row_c = warp_n * 32 + ((tid >> 4) & 1) * 8 + (tid & 7);
    const int b_k_c   = ((tid >> 3) & 1) * 16;

    // 3 products: (1,1), (1,2), (2,1)
    const int pa[3] = {0, 0, 1};
    const int pb[3] = {0, 1, 0};

    const int nch = Kdim / KC;
    for (int ch = 0; ch < nch; ch++) {
        if (MODE == 1) {
            copy2(smb + 2 * TILE_BYTES, Bh1, Bh2, tN, ldb, ch * KC, tid);
            CP_COMMIT();
            fill_clean2(smA, A + (size_t)tM * lda + ch * KC, lda, tid);
            CP_WAIT0();
        } else if (MODE == 2) {
            copy2(smb, Ah1, Ah2, tM, lda, ch * KC, tid);
            CP_COMMIT();
            fill_trans2(smB, B + (size_t)(ch * KC) * ldb + tN, ldb, tid);
            CP_WAIT0();
        } else {
            fill_clean2(smA, A + (size_t)tM * lda + ch * KC, lda, tid);
            fill_trans2(smB, B + (size_t)(ch * KC) * ldb + tN, ldb, tid);
        }
        __syncthreads();

#pragma unroll
        for (int p = 0; p < 3; p++) {
            const uint32_t baseA = smb + (uint32_t)pa[p] * TILE_BYTES;
            const uint32_t baseB = smb + (uint32_t)(2 + pb[p]) * TILE_BYTES;
#pragma unroll
            for (int ks = 0; ks < 4; ks++) {
                uint32_t af[4][4];
#pragma unroll
                for (int mf = 0; mf < 4; mf++)
                    ldsm4(af[mf], baseA + swz((uint32_t)(a_row_c + mf * 16) * 128u
                                              + (uint32_t)(a_k_c + ks * 32)));
                uint32_t bf[2][4];
#pragma unroll
                for (int jj = 0; jj < 2; jj++)
                    ldsm4(bf[jj], baseB + swz((uint32_t)(b_row_c + jj * 16) * 128u
                                              + (uint32_t)(b_k_c + ks * 32)));
#pragma unroll
                for (int mf = 0; mf < 4; mf++)
#pragma unroll
                    for (int nf = 0; nf < 4; nf++)
                        mma16816(acc[mf][nf], af[mf], &bf[nf >> 1][(nf & 1) * 2]);
            }
        }
        __syncthreads();
    }

    // -------------------- epilogue --------------------
#pragma unroll
    for (int mf = 0; mf < 4; mf++) {
        const int r0 = tM + warp_m * 64 + mf * 16 + (lane >> 2);
        const int r1 = r0 + 8;
        float sc0 = 1.f, sh0 = 0.f, sc1 = 1.f, sh1 = 0.f;
        if (MODE == 0) {
            sc0 = p0[r0] * rsqrtf(p3[r0] + 1e-5f);
            sh0 = p1[r0] - p2[r0] * sc0;
            sc1 = p0[r1] * rsqrtf(p3[r1] + 1e-5f);
            sh1 = p1[r1] - p2[r1] * sc1;
        } else if (MODE == 2) {
            sh0 = p0[r0];
            sh1 = p0[r1];
        }
#pragma unroll
        for (int nf = 0; nf < 4; nf++) {
            const int col = tN + warp_n * 32 + nf * 8 + (lane & 3) * 2;
            float v0 = acc[mf][nf][0], v1 = acc[mf][nf][1];
            float v2 = acc[mf][nf][2], v3 = acc[mf][nf][3];
            if (MODE == 0) {
                v0 = fmaxf(v0 * sc0 + sh0, 0.f);
                v1 = fmaxf(v1 * sc0 + sh0, 0.f);
                v2 = fmaxf(v2 * sc1 + sh1, 0.f);
                v3 = fmaxf(v3 * sc1 + sh1, 0.f);
                unsigned short a1, b1, a2, b2;
                const size_t o0 = kbo + (size_t)r0 * SP + col;
                split2(v0, a1, b1); split2(v1, a2, b2);
                *(uint32_t*)(g_k1 + o0) = (uint32_t)a1 | ((uint32_t)a2 << 16);
                *(uint32_t*)(g_k2 + o0) = (uint32_t)b1 | ((uint32_t)b2 << 16);
                const size_t o1 = kbo + (size_t)r1 * SP + col;
                split2(v2, a1, b1); split2(v3, a2, b2);
                *(uint32_t*)(g_k1 + o1) = (uint32_t)a1 | ((uint32_t)a2 << 16);
                *(uint32_t*)(g_k2 + o1) = (uint32_t)b1 | ((uint32_t)b2 << 16);
            } else if (MODE == 1) {
                *(float2*)(C + (size_t)r0 * COUT + col) = make_float2(v0, v1);
                *(float2*)(C + (size_t)r1 * COUT + col) = make_float2(v2, v3);
            } else {
                v0 += sh0; v1 += sh0; v2 += sh1; v3 += sh1;
                *(float2*)(C + (size_t)r0 * SP + col) = make_float2(v0, v1);
                *(float2*)(C + (size_t)r1 * SP + col) = make_float2(v2, v3);
            }
        }
    }
}

// ---------------------------------------------------------------------------
// Fused split-reduce + softmax: softmax(max-e) == exp(min-e)/sum.
// ---------------------------------------------------------------------------
__global__ void __launch_bounds__(256) softmax_k()
{
    const int nd = blockIdx.x;
    const int n = nd / DDIM;
    const int d = nd % DDIM;
    const int c = threadIdx.x;

    float e = 0.f;
#pragma unroll
    for (int s = 0; s < NSPLIT; s++)
        e += g_epart[((size_t)(n * NSPLIT + s) * DDIM + d) * COUT + c];

    __shared__ float red[256];
    red[c] = e;
    __syncthreads();
    for (int off = 128; off > 0; off >>= 1) {
        if (c < off) red[c] = fminf(red[c], red[c + off]);
        __syncthreads();
    }
    const float emin = red[0];
    __syncthreads();

    const float ex = expf(emin - e);
    red[c] = ex;
    __syncthreads();
    for (int off = 128; off > 0; off >>= 1) {
        if (c < off) red[c] += red[c + off];
        __syncthreads();
    }
    g_att[(size_t)nd * COUT + c] = ex / red[0];
}

// ---------------------------------------------------------------------------
// M[o,d] = sum_c W2[o,c] * att[d,c]; epilogue writes fp16 2-way splits.
// ---------------------------------------------------------------------------
__global__ void __launch_bounds__(256) mmul_k(const float* __restrict__ w2)
{
    const int n = blockIdx.z;
    const float* A = w2;
    const float* B = g_att + (size_t)n * DDIM * COUT;

    const int tI = blockIdx.y * 32;
    const int tJ = blockIdx.x * 32;

    __shared__ float As[32][33];
    __shared__ float Bs[32][33];

    const int tid = threadIdx.x;
    const int r  = tid >> 3;
    const int c4 = (tid & 7) * 4;
    const int io = (tid >> 4) * 2;
    const int jo = (tid & 15) * 2;

    float acc[2][2] = {{0.f, 0.f}, {0.f, 0.f}};

    for (int k0 = 0; k0 < COUT; k0 += 32) {
        float4 av = *(const float4*)(A + (size_t)(tI + r) * COUT + k0 + c4);
        float4 bv = *(const float4*)(B + (size_t)(tJ + r) * COUT + k0 + c4);
        __syncthreads();
        As[c4 + 0][r] = av.x; As[c4 + 1][r] = av.y;
        As[c4 + 2][r] = av.z; As[c4 + 3][r] = av.w;
        Bs[c4 + 0][r] = bv.x; Bs[c4 + 1][r] = bv.y;
        Bs[c4 + 2][r] = bv.z; Bs[c4 + 3][r] = bv.w;
        __syncthreads();
#pragma unroll
        for (int k = 0; k < 32; k++) {
            float a0 = As[k][io], a1 = As[k][io + 1];
            float b0 = Bs[k][jo], b1 = Bs[k][jo + 1];
            acc[0][0] = fmaf(a0, b0, acc[0][0]);
            acc[0][1] = fmaf(a0, b1, acc[0][1]);
            acc[1][0] = fmaf(a1, b0, acc[1][0]);
            acc[1][1] = fmaf(a1, b1, acc[1][1]);
        }
    }
#pragma unroll
    for (int i = 0; i < 2; i++)
#pragma unroll
        for (int j = 0; j < 2; j++) {
            unsigned short a, b;
            split2(acc[i][j], a, b);
            const size_t off = (size_t)n * COUT * DDIM
                             + (size_t)(tI + io + i) * DDIM + tJ + jo + j;
            g_m1[off] = a;
            g_m2[off] = b;
        }
}

// ---------------------------------------------------------------------------
extern "C" void kernel_launch(void* const* d_in, const int* in_sizes, int n_in,
                              void* d_out, int out_size)
{
    const float* feat  = (const float*)d_in[0];
    const float* q     = (const float*)d_in[1];
    const float* w1    = (const float*)d_in[2];
    const float* gamma = (const float*)d_in[3];
    const float* beta  = (const float*)d_in[4];
    const float* mean  = (const float*)d_in[5];
    const float* var   = (const float*)d_in[6];
    const float* w2    = (const float*)d_in[7];
    const float* b2    = (const float*)d_in[8];
    float* out = (float*)d_out;

    cudaFuncSetAttribute(tc_gemm<0>, cudaFuncAttributeMaxDynamicSharedMemorySize, SMEM_DYN);
    cudaFuncSetAttribute(tc_gemm<1>, cudaFuncAttributeMaxDynamicSharedMemorySize, SMEM_DYN);
    cudaFuncSetAttribute(tc_gemm<2>, cudaFuncAttributeMaxDynamicSharedMemorySize, SMEM_DYN);

    // 1) conv1: K = relu(bn(W1 @ F)) -> g_k fp16 splits
    tc_gemm<0><<<dim3(SP / TILE, COUT / TILE, NB), 256, SMEM_DYN>>>(
        w1, feat, nullptr, gamma, beta, mean, var);

    // 2) energy partials: E[d,c] = Q . K^T, split-S
    tc_gemm<1><<<dim3(COUT / TILE, DDIM / TILE, NB * NSPLIT), 256, SMEM_DYN>>>(
        q, nullptr, nullptr, nullptr, nullptr, nullptr, nullptr);

    // 3) reduce + softmax -> attention
    softmax_k<<<NB * DDIM, 256>>>();

    // 4) M = W2 @ att^T -> g_m fp16 splits
    mmul_k<<<dim3(DDIM / 32, COUT / 32, NB), 256>>>(w2);

    // 5) out = M @ Q + b2
    tc_gemm<2><<<dim3(SP / TILE, COUT / TILE, NB), 256, SMEM_DYN>>>(
        nullptr, q, out, b2, nullptr, nullptr, nullptr);
}

// round 13
// speedup vs baseline: 2.0133x; 1.1028x over previous
#include <cuda_runtime.h>
#include <cuda_fp16.h>
#include <cstdint>

// Problem constants
#define NB     4
#define CIN    512
#define COUT   256
#define DDIM   256
#define SP     16384            // H*W
#define NSPLIT 16
#define SCHUNK (SP / NSPLIT)    // 1024

#define TILE   128
#define KC     64               // K per chunk for conv1/conv2 (128B rows)
#define TILE_BYTES (TILE * KC * 2)      // 16384
#define SMEM_DYN   (4 * TILE_BYTES)     // 65536
// energy kernel: KC=32, 64B rows, tile 8 KiB, 2 bufs x 4 tiles
#define ETILE_B 8192
#define EBUF_B  (4 * ETILE_B)           // 32768
#define ESMEM   (2 * EBUF_B)            // 65536

// ------------------- global scratch -----------------------------------------
__device__ unsigned short g_k1[(size_t)NB * COUT * SP];   // K fp16 split hi
__device__ unsigned short g_k2[(size_t)NB * COUT * SP];   // K fp16 split lo
__device__ unsigned short g_qc1[(size_t)NB * DDIM * SP];  // q clean split hi
__device__ unsigned short g_qc2[(size_t)NB * DDIM * SP];  // q clean split lo
__device__ unsigned short g_w1s1[COUT * CIN];             // w1 split hi
__device__ unsigned short g_w1s2[COUT * CIN];             // w1 split lo
__device__ unsigned short g_m1[(size_t)NB * COUT * DDIM]; // M fp16 split hi
__device__ unsigned short g_m2[(size_t)NB * COUT * DDIM]; // M fp16 split lo
__device__ float g_epart[(size_t)NB * NSPLIT * DDIM * COUT];  // 16 MiB
__device__ float g_att[(size_t)NB * DDIM * COUT];             // 1 MiB

// ---------------- helpers ---------------------------------------------------
__device__ __forceinline__ uint32_t smem_u32(const void* p) {
    uint32_t a;
    asm("{ .reg .u64 t; cvta.to.shared.u64 t, %1; cvt.u32.u64 %0, t; }"
        : "=r"(a) : "l"(p));
    return a;
}
__device__ __forceinline__ uint32_t swz(uint32_t b)   { return b ^ ((b >> 3) & 0x70); }
__device__ __forceinline__ uint32_t swz64(uint32_t b) { return b ^ ((b >> 3) & 0x30); }

__device__ __forceinline__ void ldsm4(uint32_t* r, uint32_t addr)
{
    asm volatile("ldmatrix.sync.aligned.m8n8.x4.shared.b16 {%0,%1,%2,%3}, [%4];"
                 : "=r"(r[0]), "=r"(r[1]), "=r"(r[2]), "=r"(r[3]) : "r"(addr));
}
// D += A*B  (m16n8k16, fp16 in, fp32 acc)
__device__ __forceinline__ void mma16816(float* c, const uint32_t* a, const uint32_t* b)
{
    asm volatile(
        "mma.sync.aligned.m16n8k16.row.col.f32.f16.f16.f32 "
        "{%0,%1,%2,%3}, {%4,%5,%6,%7}, {%8,%9}, {%0,%1,%2,%3};"
        : "+f"(c[0]), "+f"(c[1]), "+f"(c[2]), "+f"(c[3])
        : "r"(a[0]), "r"(a[1]), "r"(a[2]), "r"(a[3]), "r"(b[0]), "r"(b[1]));
}
#define CP16(dst, src) asm volatile( \
    "cp.async.cg.shared.global [%0], [%1], 16;" :: "r"(dst), "l"(src) : "memory")
#define CP_COMMIT() asm volatile("cp.async.commit_group;" ::: "memory")
#define CP_WAIT0()  asm volatile("cp.async.wait_group 0;" ::: "memory")

// Split fp32 -> 2 fp16 components (x ~= h1 + h2)
__device__ __forceinline__ void split2(float x, unsigned short& a, unsigned short& b)
{
    __half h1 = __float2half_rn(x);
    float r = x - __half2float(h1);
    __half h2 = __float2half_rn(r);
    a = __half_as_ushort(h1);
    b = __half_as_ushort(h2);
}

// Transposed fill from fp32: tile[n][k] = g[k][n]. g at (k-row 0, col n0).
// 128B rows (KC=64), SW128 swizzle, 2 split tiles.
__device__ __forceinline__ void fill_trans2(char* tiles, const float* g, int ld, int tid)
{
    const int bk = (tid >> 2) & 15;                    // k-block 0..15
    const int bn0 = (tid & 3) | ((tid >> 6) << 2);     // n-block 0..7
#pragma unroll
    for (int it = 0; it < 2; it++) {
        const int bn = bn0 + it * 16;
        float4 rowv[4];
#pragma unroll
        for (int j = 0; j < 4; j++)
            rowv[j] = *(const float4*)(g + (size_t)(bk * 4 + j) * ld + bn * 4);
        const float* rp = (const float*)rowv;
#pragma unroll
        for (int i = 0; i < 4; i++) {
            unsigned long long u1 = 0, u2 = 0;
#pragma unroll
            for (int j = 0; j < 4; j++) {
                unsigned short a, b;
                split2(rp[j * 4 + i], a, b);
                u1 |= (unsigned long long)a << (16 * j);
                u2 |= (unsigned long long)b << (16 * j);
            }
            const uint32_t sw = swz((uint32_t)(bn * 4 + i) * 128u + (uint32_t)bk * 8u);
            *(unsigned long long*)(tiles + sw)              = u1;
            *(unsigned long long*)(tiles + TILE_BYTES + sw) = u2;
        }
    }
}

// Copy fill from fp16 split arrays via cp.async (KC=64, 128B rows, SW128).
__device__ __forceinline__ void copy2(uint32_t dstbase,
    const unsigned short* s1, const unsigned short* s2,
    int row0, int ld, int koff, int tid)
{
    const int r = tid >> 1;              // 0..127
    const int h = tid & 1;
#pragma unroll
    for (int j = 0; j < 4; j++) {
        const int u = h * 4 + j;         // 16B unit within 128B row
        const uint32_t dsw = swz((uint32_t)r * 128u + (uint32_t)u * 16u);
        const size_t so = (size_t)(row0 + r) * ld + koff + u * 8;
        CP16(dstbase + dsw, s1 + so);
        CP16(dstbase + TILE_BYTES + dsw, s2 + so);
    }
}

// ---------------------------------------------------------------------------
// Preconversion kernels
// ---------------------------------------------------------------------------
__global__ void __launch_bounds__(256) split_clean_k(
    const float4* __restrict__ in, ushort4* __restrict__ o1,
    ushort4* __restrict__ o2, size_t n4)
{
    size_t i = (size_t)blockIdx.x * 256 + threadIdx.x;
    if (i >= n4) return;
    float4 v = in[i];
    unsigned short a1,b1,a2,b2,a3,b3,a4,b4;
    split2(v.x, a1, b1); split2(v.y, a2, b2);
    split2(v.z, a3, b3); split2(v.w, a4, b4);
    o1[i] = make_ushort4(a1, a2, a3, a4);
    o2[i] = make_ushort4(b1, b2, b3, b4);
}

// ---------------------------------------------------------------------------
// conv1 / conv2 GEMM (KC=64, single-buffered, 2 CTAs/SM) — proven R12 core.
//   MODE 0: A = w1 splits (cp.async), B = feat fp32 trans (in-loop convert),
//           epi BN+ReLU -> K splits
//   MODE 2: A = M splits (cp.async),  B = q fp32 trans (in-loop convert),
//           epi +bias -> out
// ---------------------------------------------------------------------------
template <int MODE>
__global__ void __launch_bounds__(256) tc_gemm(
    const float* __restrict__ Bf32, float* __restrict__ outp,
    const float* __restrict__ p0, const float* __restrict__ p1,
    const float* __restrict__ p2, const float* __restrict__ p3)
{
    extern __shared__ char sm[];
    const uint32_t smb = smem_u32(sm);
    const int tid = threadIdx.x;
    const int wid = tid >> 5;
    const int lane = tid & 31;
    const int warp_m = wid >> 2;
    const int warp_n = wid & 3;

    const unsigned short *Ah1, *Ah2;
    const float* B;
    float* C = nullptr;
    int lda, ldb, Kdim;
    size_t kbo = 0;

    if (MODE == 0) {
        const int n = blockIdx.z;
        Ah1 = g_w1s1; Ah2 = g_w1s2; lda = CIN;
        B = Bf32 + (size_t)n * CIN * SP; ldb = SP;   // feat [CIN][SP]
        Kdim = CIN;
        kbo = (size_t)n * COUT * SP;
    } else {
        const int n = blockIdx.z;
        const size_t ao = (size_t)n * COUT * DDIM;
        Ah1 = g_m1 + ao; Ah2 = g_m2 + ao; lda = DDIM;
        B = Bf32 + (size_t)n * DDIM * SP; ldb = SP;  // q [DDIM][SP]
        C = outp + (size_t)n * COUT * SP;
        Kdim = DDIM;
    }
    const int tM = blockIdx.y * TILE;
    const int tN = blockIdx.x * TILE;

    char* smB = sm + 2 * TILE_BYTES;

    float acc[4][4][4];
#pragma unroll
    for (int i = 0; i < 4; i++)
#pragma unroll
        for (int j = 0; j < 4; j++)
#pragma unroll
            for (int v = 0; v < 4; v++) acc[i][j][v] = 0.f;

    const int a_row_c = warp_m * 64 + ((tid >> 3) & 1) * 8 + (tid & 7);
    const int a_k_c   = ((tid >> 4) & 1) * 16;
    const int b_row_c = warp_n * 32 + ((tid >> 4) & 1) * 8 + (tid & 7);
    const int b_k_c   = ((tid >> 3) & 1) * 16;

    const int pa[3] = {0, 0, 1};
    const int pb[3] = {0, 1, 0};

    const int nch = Kdim / KC;
    for (int ch = 0; ch < nch; ch++) {
        copy2(smb, Ah1, Ah2, tM, lda, ch * KC, tid);
        CP_COMMIT();
        fill_trans2(smB, B + (size_t)(ch * KC) * ldb + tN, ldb, tid);
        CP_WAIT0();
        __syncthreads();

#pragma unroll
        for (int p = 0; p < 3; p++) {
            const uint32_t baseA = smb + (uint32_t)pa[p] * TILE_BYTES;
            const uint32_t baseB = smb + (uint32_t)(2 + pb[p]) * TILE_BYTES;
#pragma unroll
            for (int ks = 0; ks < 4; ks++) {
                uint32_t af[4][4];
#pragma unroll
                for (int mf = 0; mf < 4; mf++)
                    ldsm4(af[mf], baseA + swz((uint32_t)(a_row_c + mf * 16) * 128u
                                              + (uint32_t)(a_k_c + ks * 32)));
                uint32_t bf[2][4];
#pragma unroll
                for (int jj = 0; jj < 2; jj++)
                    ldsm4(bf[jj], baseB + swz((uint32_t)(b_row_c + jj * 16) * 128u
                                              + (uint32_t)(b_k_c + ks * 32)));
#pragma unroll
                for (int mf = 0; mf < 4; mf++)
#pragma unroll
                    for (int nf = 0; nf < 4; nf++)
                        mma16816(acc[mf][nf], af[mf], &bf[nf >> 1][(nf & 1) * 2]);
            }
        }
        __syncthreads();
    }

    // -------------------- epilogue --------------------
#pragma unroll
    for (int mf = 0; mf < 4; mf++) {
        const int r0 = tM + warp_m * 64 + mf * 16 + (lane >> 2);
        const int r1 = r0 + 8;
        float sc0 = 1.f, sh0 = 0.f, sc1 = 1.f, sh1 = 0.f;
        if (MODE == 0) {
            sc0 = p0[r0] * rsqrtf(p3[r0] + 1e-5f);
            sh0 = p1[r0] - p2[r0] * sc0;
            sc1 = p0[r1] * rsqrtf(p3[r1] + 1e-5f);
            sh1 = p1[r1] - p2[r1] * sc1;
        } else {
            sh0 = p0[r0];
            sh1 = p0[r1];
        }
#pragma unroll
        for (int nf = 0; nf < 4; nf++) {
            const int col = tN + warp_n * 32 + nf * 8 + (lane & 3) * 2;
            float v0 = acc[mf][nf][0], v1 = acc[mf][nf][1];
            float v2 = acc[mf][nf][2], v3 = acc[mf][nf][3];
            if (MODE == 0) {
                v0 = fmaxf(v0 * sc0 + sh0, 0.f);
                v1 = fmaxf(v1 * sc0 + sh0, 0.f);
                v2 = fmaxf(v2 * sc1 + sh1, 0.f);
                v3 = fmaxf(v3 * sc1 + sh1, 0.f);
                unsigned short a1, b1, a2, b2;
                const size_t o0 = kbo + (size_t)r0 * SP + col;
                split2(v0, a1, b1); split2(v1, a2, b2);
                *(uint32_t*)(g_k1 + o0) = (uint32_t)a1 | ((uint32_t)a2 << 16);
                *(uint32_t*)(g_k2 + o0) = (uint32_t)b1 | ((uint32_t)b2 << 16);
                const size_t o1 = kbo + (size_t)r1 * SP + col;
                split2(v2, a1, b1); split2(v3, a2, b2);
                *(uint32_t*)(g_k1 + o1) = (uint32_t)a1 | ((uint32_t)a2 << 16);
                *(uint32_t*)(g_k2 + o1) = (uint32_t)b1 | ((uint32_t)b2 << 16);
            } else {
                v0 += sh0; v1 += sh0; v2 += sh1; v3 += sh1;
                *(float2*)(C + (size_t)r0 * SP + col) = make_float2(v0, v1);
                *(float2*)(C + (size_t)r1 * SP + col) = make_float2(v2, v3);
            }
        }
    }
}

// ---------------------------------------------------------------------------
// Energy GEMM: E[d,c] partials. KC=32, 64B rows, SW64 swizzle, true
// double-buffered cp.async (both operands preconverted). 2 CTAs/SM.
// grid = (COUT/128, DDIM/128, NB*NSPLIT)
// ---------------------------------------------------------------------------
__global__ void __launch_bounds__(256, 2) energy_tc()
{
    extern __shared__ char sm[];
    const uint32_t smb = smem_u32(sm);
    const int tid = threadIdx.x;
    const int wid = tid >> 5;
    const int lane = tid & 31;
    const int warp_m = wid >> 2;
    const int warp_n = wid & 3;

    const int n = blockIdx.z >> 4, sp = blockIdx.z & 15;
    const size_t ao = (size_t)n * DDIM * SP + (size_t)sp * SCHUNK;
    const size_t bo = (size_t)n * COUT * SP + (size_t)sp * SCHUNK;
    float* C = g_epart + (size_t)blockIdx.z * DDIM * COUT;
    const int tM = blockIdx.y * TILE;
    const int tN = blockIdx.x * TILE;

    const unsigned short* srcs[4] = {g_qc1 + ao, g_qc2 + ao, g_k1 + bo, g_k2 + bo};
    const int rowb[4] = {tM, tM, tN, tN};

    // cp fill mapping: thread -> (row = tid>>2 [+64], chunk c = tid&3)
    const int fr = tid >> 2;
    const int fc = tid & 3;

    float acc[4][4][4];
#pragma unroll
    for (int i = 0; i < 4; i++)
#pragma unroll
        for (int j = 0; j < 4; j++)
#pragma unroll
            for (int v = 0; v < 4; v++) acc[i][j][v] = 0.f;

    const int a_row_c = warp_m * 64 + ((tid >> 3) & 1) * 8 + (tid & 7);
    const int a_k_c   = ((tid >> 4) & 1) * 16;
    const int b_row_c = warp_n * 32 + ((tid >> 4) & 1) * 8 + (tid & 7);
    const int b_k_c   = ((tid >> 3) & 1) * 16;

    const int pa[3] = {0, 0, 1};
    const int pb[3] = {0, 1, 0};

    const int nch = SCHUNK / 32;   // 32 chunks

    // prologue: fill buffer 0 with chunk 0
    {
        const uint32_t bse = smb;
#pragma unroll
        for (int t = 0; t < 4; t++)
#pragma unroll
            for (int h = 0; h < 2; h++) {
                const int r = fr + h * 64;
                CP16(bse + t * ETILE_B + swz64((uint32_t)r * 64u + (uint32_t)fc * 16u),
                     srcs[t] + (size_t)(rowb[t] + r) * SP + fc * 8);
            }
        CP_COMMIT();
    }

    for (int ch = 0; ch < nch; ch++) {
        CP_WAIT0();
        __syncthreads();
        if (ch + 1 < nch) {
            const uint32_t bse = smb + (uint32_t)((ch + 1) & 1) * EBUF_B;
            const int koff = (ch + 1) * 32;
#pragma unroll
            for (int t = 0; t < 4; t++)
#pragma unroll
                for (int h = 0; h < 2; h++) {
                    const int r = fr + h * 64;
                    CP16(bse + t * ETILE_B + swz64((uint32_t)r * 64u + (uint32_t)fc * 16u),
                         srcs[t] + (size_t)(rowb[t] + r) * SP + koff + fc * 8);
                }
            CP_COMMIT();
        }

        const uint32_t cb = smb + (uint32_t)(ch & 1) * EBUF_B;
#pragma unroll
        for (int p = 0; p < 3; p++) {
            const uint32_t baseA = cb + (uint32_t)pa[p] * ETILE_B;
            const uint32_t baseB = cb + (uint32_t)(2 + pb[p]) * ETILE_B;
#pragma unroll
            for (int ks = 0; ks < 2; ks++) {
                uint32_t af[4][4];
#pragma unroll
                for (int mf = 0; mf < 4; mf++)
                    ldsm4(af[mf], baseA + swz64((uint32_t)(a_row_c + mf * 16) * 64u
                                                + (uint32_t)(a_k_c + ks * 32)));
                uint32_t bf[2][4];
#pragma unroll
                for (int jj = 0; jj < 2; jj++)
                    ldsm4(bf[jj], baseB + swz64((uint32_t)(b_row_c + jj * 16) * 64u
                                                + (uint32_t)(b_k_c + ks * 32)));
#pragma unroll
                for (int mf = 0; mf < 4; mf++)
#pragma unroll
                    for (int nf = 0; nf < 4; nf++)
                        mma16816(acc[mf][nf], af[mf], &bf[nf >> 1][(nf & 1) * 2]);
            }
        }
    }

    // epilogue: fp32 partials
#pragma unroll
    for (int mf = 0; mf < 4; mf++) {
        const int r0 = tM + warp_m * 64 + mf * 16 + (lane >> 2);
        const int r1 = r0 + 8;
#pragma unroll
        for (int nf = 0; nf < 4; nf++) {
            const int col = tN + warp_n * 32 + nf * 8 + (lane & 3) * 2;
            *(float2*)(C + (size_t)r0 * COUT + col)
                = make_float2(acc[mf][nf][0], acc[mf][nf][1]);
            *(float2*)(C + (size_t)r1 * COUT + col)
                = make_float2(acc[mf][nf][2], acc[mf][nf][3]);
        }
    }
}

// ---------------------------------------------------------------------------
// Fused split-reduce + softmax: softmax(max-e) == exp(min-e)/sum.
// ---------------------------------------------------------------------------
__global__ void __launch_bounds__(256) softmax_k()
{
    const int nd = blockIdx.x;
    const int n = nd / DDIM;
    const int d = nd % DDIM;
    const int c = threadIdx.x;

    float e = 0.f;
#pragma unroll
    for (int s = 0; s < NSPLIT; s++)
        e += g_epart[((size_t)(n * NSPLIT + s) * DDIM + d) * COUT + c];

    __shared__ float red[256];
    red[c] = e;
    __syncthreads();
    for (int off = 128; off > 0; off >>= 1) {
        if (c < off) red[c] = fminf(red[c], red[c + off]);
        __syncthreads();
    }
    const float emin = red[0];
    __syncthreads();

    const float ex = expf(emin - e);
    red[c] = ex;
    __syncthreads();
    for (int off = 128; off > 0; off >>= 1) {
        if (c < off) red[c] += red[c + off];
        __syncthreads();
    }
    g_att[(size_t)nd * COUT + c] = ex / red[0];
}

// ---------------------------------------------------------------------------
// M[o,d] = sum_c W2[o,c] * att[d,c]; epilogue writes fp16 2-way splits.
// ---------------------------------------------------------------------------
__global__ void __launch_bounds__(256) mmul_k(const float* __restrict__ w2)
{
    const int n = blockIdx.z;
    const float* A = w2;
    const float* B = g_att + (size_t)n * DDIM * COUT;

    const int tI = blockIdx.y * 32;
    const int tJ = blockIdx.x * 32;

    __shared__ float As[32][33];
    __shared__ float Bs[32][33];

    const int tid = threadIdx.x;
    const int r  = tid >> 3;
    const int c4 = (tid & 7) * 4;
    const int io = (tid >> 4) * 2;
    const int jo = (tid & 15) * 2;

    float acc[2][2] = {{0.f, 0.f}, {0.f, 0.f}};

    for (int k0 = 0; k0 < COUT; k0 += 32) {
        float4 av = *(const float4*)(A + (size_t)(tI + r) * COUT + k0 + c4);
        float4 bv = *(const float4*)(B + (size_t)(tJ + r) * COUT + k0 + c4);
        __syncthreads();
        As[c4 + 0][r] = av.x; As[c4 + 1][r] = av.y;
        As[c4 + 2][r] = av.z; As[c4 + 3][r] = av.w;
        Bs[c4 + 0][r] = bv.x; Bs[c4 + 1][r] = bv.y;
        Bs[c4 + 2][r] = bv.z; Bs[c4 + 3][r] = bv.w;
        __syncthreads();
#pragma unroll
        for (int k = 0; k < 32; k++) {
            float a0 = As[k][io], a1 = As[k][io + 1];
            float b0 = Bs[k][jo], b1 = Bs[k][jo + 1];
            acc[0][0] = fmaf(a0, b0, acc[0][0]);
            acc[0][1] = fmaf(a0, b1, acc[0][1]);
            acc[1][0] = fmaf(a1, b0, acc[1][0]);
            acc[1][1] = fmaf(a1, b1, acc[1][1]);
        }
    }
#pragma unroll
    for (int i = 0; i < 2; i++)
#pragma unroll
        for (int j = 0; j < 2; j++) {
            unsigned short a, b;
            split2(acc[i][j], a, b);
            const size_t off = (size_t)n * COUT * DDIM
                             + (size_t)(tI + io + i) * DDIM + tJ + jo + j;
            g_m1[off] = a;
            g_m2[off] = b;
        }
}

// ---------------------------------------------------------------------------
extern "C" void kernel_launch(void* const* d_in, const int* in_sizes, int n_in,
                              void* d_out, int out_size)
{
    const float* feat  = (const float*)d_in[0];
    const float* q     = (const float*)d_in[1];
    const float* w1    = (const float*)d_in[2];
    const float* gamma = (const float*)d_in[3];
    const float* beta  = (const float*)d_in[4];
    const float* mean  = (const float*)d_in[5];
    const float* var   = (const float*)d_in[6];
    const float* w2    = (const float*)d_in[7];
    const float* b2    = (const float*)d_in[8];
    float* out = (float*)d_out;

    void *qc1, *qc2, *w1s1, *w1s2;
    cudaGetSymbolAddress(&qc1, g_qc1);   cudaGetSymbolAddress(&qc2, g_qc2);
    cudaGetSymbolAddress(&w1s1, g_w1s1); cudaGetSymbolAddress(&w1s2, g_w1s2);

    cudaFuncSetAttribute(tc_gemm<0>, cudaFuncAttributeMaxDynamicSharedMemorySize, SMEM_DYN);
    cudaFuncSetAttribute(tc_gemm<2>, cudaFuncAttributeMaxDynamicSharedMemorySize, SMEM_DYN);
    cudaFuncSetAttribute(energy_tc,  cudaFuncAttributeMaxDynamicSharedMemorySize, ESMEM);

    // 0a) q -> clean fp16 splits
    {
        size_t n4 = (size_t)NB * DDIM * SP / 4;
        split_clean_k<<<(unsigned)((n4 + 255) / 256), 256>>>(
            (const float4*)q, (ushort4*)qc1, (ushort4*)qc2, n4);
    }
    // 0b) w1 -> fp16 splits
    {
        size_t n4 = (size_t)COUT * CIN / 4;
        split_clean_k<<<(unsigned)((n4 + 255) / 256), 256>>>(
            (const float4*)w1, (ushort4*)w1s1, (ushort4*)w1s2, n4);
    }

    // 1) conv1: K = relu(bn(W1 @ F)) -> g_k fp16 splits
    tc_gemm<0><<<dim3(SP / TILE, COUT / TILE, NB), 256, SMEM_DYN>>>(
        feat, nullptr, gamma, beta, mean, var);

    // 2) energy partials: E[d,c] = Q . K^T, split-S, double-buffered cp.async
    energy_tc<<<dim3(COUT / TILE, DDIM / TILE, NB * NSPLIT), 256, ESMEM>>>();

    // 3) reduce + softmax -> attention
    softmax_k<<<NB * DDIM, 256>>>();

    // 4) M = W2 @ att^T -> g_m fp16 splits
    mmul_k<<<dim3(DDIM / 32, COUT / 32, NB), 256>>>(w2);

    // 5) out = M @ Q + b2
    tc_gemm<2><<<dim3(SP / TILE, COUT / TILE, NB), 256, SMEM_DYN>>>(
        q, out, b2, nullptr, nullptr, nullptr);
}

// round 15
// speedup vs baseline: 2.5132x; 1.2483x over previous
#include <cuda_runtime.h>
#include <cuda_fp16.h>
#include <cstdint>

// Problem constants
#define NB     4
#define CIN    512
#define COUT   256
#define DDIM   256
#define SP     16384            // H*W
#define NSPLIT 16
#define SCHUNK (SP / NSPLIT)    // 1024

#define TILE   128
#define T8K    8192             // one split tile: A [128][32] or B [32][128] fp16
#define BUF_B  (4 * T8K)        // A1 A2 B1 B2
#define SMEM2  (2 * BUF_B)      // 65536, double buffered

// ------------------- global scratch -----------------------------------------
__device__ unsigned short g_f1[(size_t)NB * CIN * SP];    // feat split hi [n][cin][s]
__device__ unsigned short g_f2[(size_t)NB * CIN * SP];    // feat split lo
__device__ unsigned short g_qc1[(size_t)NB * DDIM * SP];  // q split hi [n][d][s]
__device__ unsigned short g_qc2[(size_t)NB * DDIM * SP];  // q split lo
__device__ unsigned short g_k1[(size_t)NB * COUT * SP];   // K split hi [n][c][s]
__device__ unsigned short g_k2[(size_t)NB * COUT * SP];   // K split lo
__device__ unsigned short g_w1s1[COUT * CIN];             // w1 split hi
__device__ unsigned short g_w1s2[COUT * CIN];             // w1 split lo
__device__ unsigned short g_m1[(size_t)NB * COUT * DDIM]; // M split hi [n][o][d]
__device__ unsigned short g_m2[(size_t)NB * COUT * DDIM]; // M split lo
__device__ float g_epart[(size_t)NB * NSPLIT * DDIM * COUT];  // 16 MiB
__device__ float g_att[(size_t)NB * DDIM * COUT];             // 1 MiB

// ---------------- helpers ---------------------------------------------------
__device__ __forceinline__ uint32_t smem_u32(const void* p) {
    uint32_t a;
    asm("{ .reg .u64 t; cvta.to.shared.u64 t, %1; cvt.u32.u64 %0, t; }"
        : "=r"(a) : "l"(p));
    return a;
}
// 64B-row swizzle (A tiles, B non-trans tiles)
__device__ __forceinline__ uint32_t swz64(uint32_t b)  { return b ^ ((b >> 3) & 0x30); }
// 256B-row swizzle (B trans tiles): XOR row bits [8:11) into 16B-unit bits [4:7)
__device__ __forceinline__ uint32_t swz256(uint32_t b) { return b ^ ((b >> 4) & 0x70); }

__device__ __forceinline__ void ldsm4(uint32_t* r, uint32_t addr)
{
    asm volatile("ldmatrix.sync.aligned.m8n8.x4.shared.b16 {%0,%1,%2,%3}, [%4];"
                 : "=r"(r[0]), "=r"(r[1]), "=r"(r[2]), "=r"(r[3]) : "r"(addr));
}
__device__ __forceinline__ void ldsm4_t(uint32_t* r, uint32_t addr)
{
    asm volatile("ldmatrix.sync.aligned.m8n8.x4.trans.shared.b16 {%0,%1,%2,%3}, [%4];"
                 : "=r"(r[0]), "=r"(r[1]), "=r"(r[2]), "=r"(r[3]) : "r"(addr));
}
// D += A*B  (m16n8k16, fp16 in, fp32 acc)
__device__ __forceinline__ void mma16816(float* c, const uint32_t* a, const uint32_t* b)
{
    asm volatile(
        "mma.sync.aligned.m16n8k16.row.col.f32.f16.f16.f32 "
        "{%0,%1,%2,%3}, {%4,%5,%6,%7}, {%8,%9}, {%0,%1,%2,%3};"
        : "+f"(c[0]), "+f"(c[1]), "+f"(c[2]), "+f"(c[3])
        : "r"(a[0]), "r"(a[1]), "r"(a[2]), "r"(a[3]), "r"(b[0]), "r"(b[1]));
}
#define CP16(dst, src) asm volatile( \
    "cp.async.cg.shared.global [%0], [%1], 16;" :: "r"(dst), "l"(src) : "memory")
#define CP_COMMIT() asm volatile("cp.async.commit_group;" ::: "memory")
#define CP_WAIT0()  asm volatile("cp.async.wait_group 0;" ::: "memory")

// Split fp32 -> 2 fp16 components (x ~= h1 + h2)
__device__ __forceinline__ void split2(float x, unsigned short& a, unsigned short& b)
{
    __half h1 = __float2half_rn(x);
    float r = x - __half2float(h1);
    __half h2 = __float2half_rn(r);
    a = __half_as_ushort(h1);
    b = __half_as_ushort(h2);
}

// ---------------------------------------------------------------------------
// Elementwise split kernel (coalesced, no transpose)
// ---------------------------------------------------------------------------
__global__ void __launch_bounds__(256) split_clean_k(
    const float4* __restrict__ in, ushort4* __restrict__ o1,
    ushort4* __restrict__ o2, size_t n4)
{
    size_t i = (size_t)blockIdx.x * 256 + threadIdx.x;
    if (i >= n4) return;
    float4 v = in[i];
    unsigned short a1,b1,a2,b2,a3,b3,a4,b4;
    split2(v.x, a1, b1); split2(v.y, a2, b2);
    split2(v.z, a3, b3); split2(v.w, a4, b4);
    o1[i] = make_ushort4(a1, a2, a3, a4);
    o2[i] = make_ushort4(b1, b2, b3, b4);
}

// ---------------------------------------------------------------------------
// Unified tensor-core GEMM. fp16 2-way split, 3 products, all-cp.async,
// double buffered, KC=32.
//   MODE 0 (conv1):  A=w1 splits [o][cin],  B=feat splits [cin][s] TRANS,
//                    K=512, epi BN+ReLU -> K splits [c][s]
//   MODE 1 (energy): A=q splits [d][s],     B=K splits [c][s] non-trans,
//                    K=SCHUNK (split-S via z), epi fp32 partials
//   MODE 2 (conv2):  A=M splits [o][d],     B=q splits [d][s] TRANS,
//                    K=256, epi +bias -> out
// 128x128 tile, 8 warps (2m x 4n), warp tile 64x32.
// ---------------------------------------------------------------------------
template <int MODE>
__global__ void __launch_bounds__(256, 2) tc2(
    float* __restrict__ outp,
    const float* __restrict__ p0, const float* __restrict__ p1,
    const float* __restrict__ p2, const float* __restrict__ p3)
{
    constexpr bool TRB = (MODE != 1);

    extern __shared__ char sm[];
    const uint32_t smb = smem_u32(sm);
    const int tid = threadIdx.x;
    const int wid = tid >> 5;
    const int lane = tid & 31;
    const int warp_m = wid >> 2;
    const int warp_n = wid & 3;

    const unsigned short *A1, *A2, *B1, *B2;
    float* C = nullptr;
    int lda, ldb, nch;
    size_t kbo = 0;

    if (MODE == 0) {
        const int n = blockIdx.z;
        A1 = g_w1s1; A2 = g_w1s2; lda = CIN;
        const size_t bo = (size_t)n * CIN * SP;
        B1 = g_f1 + bo; B2 = g_f2 + bo; ldb = SP;
        nch = CIN / 32;
        kbo = (size_t)n * COUT * SP;
    } else if (MODE == 1) {
        const int n = blockIdx.z >> 4, sp = blockIdx.z & 15;
        const size_t ao = (size_t)n * DDIM * SP + (size_t)sp * SCHUNK;
        A1 = g_qc1 + ao; A2 = g_qc2 + ao; lda = SP;
        const size_t bo = (size_t)n * COUT * SP + (size_t)sp * SCHUNK;
        B1 = g_k1 + bo; B2 = g_k2 + bo; ldb = SP;
        C = g_epart + (size_t)blockIdx.z * DDIM * COUT;
        nch = SCHUNK / 32;
    } else {
        const int n = blockIdx.z;
        const size_t ao = (size_t)n * COUT * DDIM;
        A1 = g_m1 + ao; A2 = g_m2 + ao; lda = DDIM;
        const size_t bo = (size_t)n * DDIM * SP;
        B1 = g_qc1 + bo; B2 = g_qc2 + bo; ldb = SP;
        C = outp + (size_t)n * COUT * SP;
        nch = DDIM / 32;
    }
    const int tM = blockIdx.y * TILE;
    const int tN = blockIdx.x * TILE;

    // fill thread mappings
    const int fr = tid >> 2;             // A rows (and B non-trans rows)
    const int fc = tid & 3;              // 16B unit within 64B row
    const int br = tid >> 3;             // B trans k-row 0..31
    const int bu = tid & 7;              // B trans 16B unit base

    auto fill = [&](uint32_t buf, int kbase) {
#pragma unroll
        for (int h = 0; h < 2; h++) {
            const int r = fr + h * 64;
            const uint32_t d = swz64((uint32_t)r * 64u + (uint32_t)fc * 16u);
            CP16(buf + d,       A1 + (size_t)(tM + r) * lda + kbase + fc * 8);
            CP16(buf + T8K + d, A2 + (size_t)(tM + r) * lda + kbase + fc * 8);
        }
        if (TRB) {
#pragma unroll
            for (int h = 0; h < 2; h++) {
                const int u = bu + h * 8;
                const uint32_t d = swz256((uint32_t)br * 256u + (uint32_t)u * 16u);
                CP16(buf + 2 * T8K + d, B1 + (size_t)(kbase + br) * ldb + tN + u * 8);
                CP16(buf + 3 * T8K + d, B2 + (size_t)(kbase + br) * ldb + tN + u * 8);
            }
        } else {
#pragma unroll
            for (int h = 0; h < 2; h++) {
                const int r = fr + h * 64;
                const uint32_t d = swz64((uint32_t)r * 64u + (uint32_t)fc * 16u);
                CP16(buf + 2 * T8K + d, B1 + (size_t)(tN + r) * ldb + kbase + fc * 8);
                CP16(buf + 3 * T8K + d, B2 + (size_t)(tN + r) * ldb + kbase + fc * 8);
            }
        }
    };

    float acc[4][4][4];
#pragma unroll
    for (int i = 0; i < 4; i++)
#pragma unroll
        for (int j = 0; j < 4; j++)
#pragma unroll
            for (int v = 0; v < 4; v++) acc[i][j][v] = 0.f;

    // ldmatrix address components
    const int a_row_c = warp_m * 64 + ((tid >> 3) & 1) * 8 + (tid & 7);
    const int a_k_c   = ((tid >> 4) & 1) * 16;   // bytes
    const int b_row_c = warp_n * 32 + ((tid >> 4) & 1) * 8 + (tid & 7);   // non-trans
    const int b_k_c   = ((tid >> 3) & 1) * 16;                            // non-trans
    const int bt_row  = ((tid >> 3) & 1) * 8 + (tid & 7);                 // trans k-row
    const int bt_u    = warp_n * 4 + ((tid >> 4) & 1);                    // trans 16B unit

    const int pa[3] = {0, 0, 1};
    const int pb[3] = {0, 1, 0};

    fill(smb, 0);
    CP_COMMIT();

    for (int ch = 0; ch < nch; ch++) {
        CP_WAIT0();
        __syncthreads();
        if (ch + 1 < nch) {
            fill(smb + (uint32_t)((ch + 1) & 1) * BUF_B, (ch + 1) * 32);
            CP_COMMIT();
        }

        const uint32_t cb = smb + (uint32_t)(ch & 1) * BUF_B;
#pragma unroll
        for (int p = 0; p < 3; p++) {
            const uint32_t baseA = cb + (uint32_t)pa[p] * T8K;
            const uint32_t baseB = cb + (uint32_t)(2 + pb[p]) * T8K;
#pragma unroll
            for (int ks = 0; ks < 2; ks++) {
                uint32_t af[4][4];
#pragma unroll
                for (int mf = 0; mf < 4; mf++)
                    ldsm4(af[mf], baseA + swz64((uint32_t)(a_row_c + mf * 16) * 64u
                                                + (uint32_t)(a_k_c + ks * 32)));
                uint32_t bf[2][4];
#pragma unroll
                for (int jj = 0; jj < 2; jj++) {
                    if (TRB) {
                        const uint32_t addr = baseB
                            + swz256((uint32_t)(ks * 16 + bt_row) * 256u
                                     + (uint32_t)(bt_u + jj * 2) * 16u);
                        ldsm4_t(bf[jj], addr);
                    } else {
                        ldsm4(bf[jj], baseB + swz64((uint32_t)(b_row_c + jj * 16) * 64u
                                                    + (uint32_t)(b_k_c + ks * 32)));
                    }
                }
#pragma unroll
                for (int mf = 0; mf < 4; mf++)
#pragma unroll
                    for (int nf = 0; nf < 4; nf++)
                        mma16816(acc[mf][nf], af[mf], &bf[nf >> 1][(nf & 1) * 2]);
            }
        }
        __syncthreads();
    }

    // -------------------- epilogue --------------------
#pragma unroll
    for (int mf = 0; mf < 4; mf++) {
        const int r0 = tM + warp_m * 64 + mf * 16 + (lane >> 2);
        const int r1 = r0 + 8;
        float sc0 = 1.f, sh0 = 0.f, sc1 = 1.f, sh1 = 0.f;
        if (MODE == 0) {
            sc0 = p0[r0] * rsqrtf(p3[r0] + 1e-5f);
            sh0 = p1[r0] - p2[r0] * sc0;
            sc1 = p0[r1] * rsqrtf(p3[r1] + 1e-5f);
            sh1 = p1[r1] - p2[r1] * sc1;
        } else if (MODE == 2) {
            sh0 = p0[r0];
            sh1 = p0[r1];
        }
#pragma unroll
        for (int nf = 0; nf < 4; nf++) {
            const int col = tN + warp_n * 32 + nf * 8 + (lane & 3) * 2;
            float v0 = acc[mf][nf][0], v1 = acc[mf][nf][1];
            float v2 = acc[mf][nf][2], v3 = acc[mf][nf][3];
            if (MODE == 0) {
                v0 = fmaxf(v0 * sc0 + sh0, 0.f);
                v1 = fmaxf(v1 * sc0 + sh0, 0.f);
                v2 = fmaxf(v2 * sc1 + sh1, 0.f);
                v3 = fmaxf(v3 * sc1 + sh1, 0.f);
                unsigned short a1, b1, a2, b2;
                const size_t o0 = kbo + (size_t)r0 * SP + col;
                split2(v0, a1, b1); split2(v1, a2, b2);
                *(uint32_t*)(g_k1 + o0) = (uint32_t)a1 | ((uint32_t)a2 << 16);
                *(uint32_t*)(g_k2 + o0) = (uint32_t)b1 | ((uint32_t)b2 << 16);
                const size_t o1 = kbo + (size_t)r1 * SP + col;
                split2(v2, a1, b1); split2(v3, a2, b2);
                *(uint32_t*)(g_k1 + o1) = (uint32_t)a1 | ((uint32_t)a2 << 16);
                *(uint32_t*)(g_k2 + o1) = (uint32_t)b1 | ((uint32_t)b2 << 16);
            } else if (MODE == 1) {
                *(float2*)(C + (size_t)r0 * COUT + col) = make_float2(v0, v1);
                *(float2*)(C + (size_t)r1 * COUT + col) = make_float2(v2, v3);
            } else {
                v0 += sh0; v1 += sh0; v2 += sh1; v3 += sh1;
                *(float2*)(C + (size_t)r0 * SP + col) = make_float2(v0, v1);
                *(float2*)(C + (size_t)r1 * SP + col) = make_float2(v2, v3);
            }
        }
    }
}

// ---------------------------------------------------------------------------
// Fused split-reduce + softmax: softmax(max-e) == exp(min-e)/sum.
// ---------------------------------------------------------------------------
__global__ void __launch_bounds__(256) softmax_k()
{
    const int nd = blockIdx.x;
    const int n = nd / DDIM;
    const int d = nd % DDIM;
    const int c = threadIdx.x;

    float e = 0.f;
#pragma unroll
    for (int s = 0; s < NSPLIT; s++)
        e += g_epart[((size_t)(n * NSPLIT + s) * DDIM + d) * COUT + c];

    __shared__ float red[256];
    red[c] = e;
    __syncthreads();
    for (int off = 128; off > 0; off >>= 1) {
        if (c < off) red[c] = fminf(red[c], red[c + off]);
        __syncthreads();
    }
    const float emin = red[0];
    __syncthreads();

    const float ex = expf(emin - e);
    red[c] = ex;
    __syncthreads();
    for (int off = 128; off > 0; off >>= 1) {
        if (c < off) red[c] += red[c + off];
        __syncthreads();
    }
    g_att[(size_t)nd * COUT + c] = ex / red[0];
}

// ---------------------------------------------------------------------------
// M[o,d] = sum_c W2[o,c] * att[d,c]; epilogue writes fp16 2-way splits.
// ---------------------------------------------------------------------------
__global__ void __launch_bounds__(256) mmul_k(const float* __restrict__ w2)
{
    const int n = blockIdx.z;
    const float* A = w2;
    const float* B = g_att + (size_t)n * DDIM * COUT;

    const int tI = blockIdx.y * 32;
    const int tJ = blockIdx.x * 32;

    __shared__ float As[32][33];
    __shared__ float Bs[32][33];

    const int tid = threadIdx.x;
    const int r  = tid >> 3;
    const int c4 = (tid & 7) * 4;
    const int io = (tid >> 4) * 2;
    const int jo = (tid & 15) * 2;

    float acc[2][2] = {{0.f, 0.f}, {0.f, 0.f}};

    for (int k0 = 0; k0 < COUT; k0 += 32) {
        float4 av = *(const float4*)(A + (size_t)(tI + r) * COUT + k0 + c4);
        float4 bv = *(const float4*)(B + (size_t)(tJ + r) * COUT + k0 + c4);
        __syncthreads();
        As[c4 + 0][r] = av.x; As[c4 + 1][r] = av.y;
        As[c4 + 2][r] = av.z; As[c4 + 3][r] = av.w;
        Bs[c4 + 0][r] = bv.x; Bs[c4 + 1][r] = bv.y;
        Bs[c4 + 2][r] = bv.z; Bs[c4 + 3][r] = bv.w;
        __syncthreads();
#pragma unroll
        for (int k = 0; k < 32; k++) {
            float a0 = As[k][io], a1 = As[k][io + 1];
            float b0 = Bs[k][jo], b1 = Bs[k][jo + 1];
            acc[0][0] = fmaf(a0, b0, acc[0][0]);
            acc[0][1] = fmaf(a0, b1, acc[0][1]);
            acc[1][0] = fmaf(a1, b0, acc[1][0]);
            acc[1][1] = fmaf(a1, b1, acc[1][1]);
        }
    }
#pragma unroll
    for (int i = 0; i < 2; i++)
#pragma unroll
        for (int j = 0; j < 2; j++) {
            unsigned short a, b;
            split2(acc[i][j], a, b);
            const size_t off = (size_t)n * COUT * DDIM
                             + (size_t)(tI + io + i) * DDIM + tJ + jo + j;
            g_m1[off] = a;
            g_m2[off] = b;
        }
}

// ---------------------------------------------------------------------------
extern "C" void kernel_launch(void* const* d_in, const int* in_sizes, int n_in,
                              void* d_out, int out_size)
{
    const float* feat  = (const float*)d_in[0];
    const float* q     = (const float*)d_in[1];
    const float* w1    = (const float*)d_in[2];
    const float* gamma = (const float*)d_in[3];
    const float* beta  = (const float*)d_in[4];
    const float* mean  = (const float*)d_in[5];
    const float* var   = (const float*)d_in[6];
    const float* w2    = (const float*)d_in[7];
    const float* b2    = (const float*)d_in[8];
    float* out = (float*)d_out;

    void *qc1, *qc2, *w1s1, *w1s2, *f1, *f2;
    cudaGetSymbolAddress(&qc1, g_qc1);   cudaGetSymbolAddress(&qc2, g_qc2);
    cudaGetSymbolAddress(&w1s1, g_w1s1); cudaGetSymbolAddress(&w1s2, g_w1s2);
    cudaGetSymbolAddress(&f1, g_f1);     cudaGetSymbolAddress(&f2, g_f2);

    cudaFuncSetAttribute(tc2<0>, cudaFuncAttributeMaxDynamicSharedMemorySize, SMEM2);
    cudaFuncSetAttribute(tc2<1>, cudaFuncAttributeMaxDynamicSharedMemorySize, SMEM2);
    cudaFuncSetAttribute(tc2<2>, cudaFuncAttributeMaxDynamicSharedMemorySize, SMEM2);

    // 0) elementwise fp16 splits (coalesced, no transpose anywhere)
    {
        size_t n4 = (size_t)NB * DDIM * SP / 4;
        split_clean_k<<<(unsigned)((n4 + 255) / 256), 256>>>(
            (const float4*)q, (ushort4*)qc1, (ushort4*)qc2, n4);
    }
    {
        size_t n4 = (size_t)NB * CIN * SP / 4;
        split_clean_k<<<(unsigned)((n4 + 255) / 256), 256>>>(
            (const float4*)feat, (ushort4*)f1, (ushort4*)f2, n4);
    }
    {
        size_t n4 = (size_t)COUT * CIN / 4;
        split_clean_k<<<(unsigned)((n4 + 255) / 256), 256>>>(
            (const float4*)w1, (ushort4*)w1s1, (ushort4*)w1s2, n4);
    }

    // 1) conv1: K = relu(bn(W1 @ F)) -> K splits
    tc2<0><<<dim3(SP / TILE, COUT / TILE, NB), 256, SMEM2>>>(
        nullptr, gamma, beta, mean, var);

    // 2) energy partials: E[d,c] = Q . K^T, split-S
    tc2<1><<<dim3(COUT / TILE, DDIM / TILE, NB * NSPLIT), 256, SMEM2>>>(
        nullptr, nullptr, nullptr, nullptr, nullptr);

    // 3) reduce + softmax -> attention
    softmax_k<<<NB * DDIM, 256>>>();

    // 4) M = W2 @ att^T -> M splits
    mmul_k<<<dim3(DDIM / 32, COUT / 32, NB), 256>>>(w2);

    // 5) out = M @ Q + b2
    tc2<2><<<dim3(SP / TILE, COUT / TILE, NB), 256, SMEM2>>>(
        out, b2, nullptr, nullptr, nullptr);
}